// round 3
// baseline (speedup 1.0000x reference)
#include <cuda_runtime.h>

#define N_ENT  100000
#define N_EDGE 1600000
#define N_REL  64

// Scratch (allocation-free rule: __device__ globals)
static __device__ float g_tailproj[N_ENT * 64];    // W_t · emb[n]
static __device__ float g_headrec [N_ENT * 128];   // [W_h·emb | M_h·emb]
static __device__ float g_self    [N_ENT * 128];   // [W_r·self_rel + b | M_r·self_rel]
static __device__ float g_arel    [N_REL * 64];    // W_r·emb_rel[r] + attn_b
static __device__ float g_mrel    [N_REL * 64];    // M_r·emb_rel[r]
static __device__ int   g_hist    [N_ENT * 64];    // per-node relation histogram
static __device__ int   g_deg     [N_ENT];         // in-degree (excl. self)
static __device__ int   g_off     [N_ENT + 1];     // CSR offsets
static __device__ int   g_cursor  [N_ENT];         // scatter cursors
static __device__ int2  g_sorted  [N_EDGE];        // (head, rel) grouped by tail

// ---------------------------------------------------------------------------
__global__ void rel_tables_kernel(const float* __restrict__ emb_rel,
                                  const float* __restrict__ attn_W,
                                  const float* __restrict__ attn_b,
                                  const float* __restrict__ aggr_W) {
    int r = threadIdx.x;
    if (r >= N_REL) return;
    float ev[32];
#pragma unroll
    for (int k = 0; k < 32; k++) ev[k] = emb_rel[r * 32 + k];
    for (int o = 0; o < 64; o++) {
        float a = attn_b[o], m = 0.f;
#pragma unroll
        for (int k = 0; k < 32; k++) {
            a = fmaf(attn_W[o * 96 + 64 + k], ev[k], a);
            m = fmaf(aggr_W[o * 64 + 32 + k], ev[k], m);
        }
        g_arel[r * 64 + o] = a;
        g_mrel[r * 64 + o] = m;
    }
}

// ---------------------------------------------------------------------------
// Per-node projections: one warp per node, lane = output dim (and dim+32)
__global__ void node_proj_kernel(const float* __restrict__ emb_ent,
                                 const float* __restrict__ attn_W,
                                 const float* __restrict__ aggr_W) {
    __shared__ float s_t[32 * 64], s_h[32 * 64], s_m[32 * 64];  // [k][o]
    for (int i = threadIdx.x; i < 2048; i += blockDim.x) {
        int k = i >> 6, o = i & 63;
        s_t[i] = attn_W[o * 96 + k];
        s_h[i] = attn_W[o * 96 + 32 + k];
        s_m[i] = aggr_W[o * 64 + k];
    }
    __syncthreads();
    int lane = threadIdx.x & 31;
    int warp = threadIdx.x >> 5;
    int wpb  = blockDim.x >> 5;
    for (int n = blockIdx.x * wpb + warp; n < N_ENT; n += gridDim.x * wpb) {
        float e = emb_ent[n * 32 + lane];
        float a0 = 0, a1 = 0, b0 = 0, b1 = 0, m0 = 0, m1 = 0;
#pragma unroll
        for (int k = 0; k < 32; k++) {
            float ek = __shfl_sync(0xffffffffu, e, k);
            a0 = fmaf(s_t[k * 64 + lane],      ek, a0);
            a1 = fmaf(s_t[k * 64 + 32 + lane], ek, a1);
            b0 = fmaf(s_h[k * 64 + lane],      ek, b0);
            b1 = fmaf(s_h[k * 64 + 32 + lane], ek, b1);
            m0 = fmaf(s_m[k * 64 + lane],      ek, m0);
            m1 = fmaf(s_m[k * 64 + 32 + lane], ek, m1);
        }
        g_tailproj[n * 64 + lane]       = a0;
        g_tailproj[n * 64 + 32 + lane]  = a1;
        g_headrec[n * 128 + lane]       = b0;
        g_headrec[n * 128 + 32 + lane]  = b1;
        g_headrec[n * 128 + 64 + lane]  = m0;
        g_headrec[n * 128 + 96 + lane]  = m1;
    }
}

// ---------------------------------------------------------------------------
__global__ void hist_kernel(const int* __restrict__ tail,
                            const int* __restrict__ rel) {
    int e = blockIdx.x * blockDim.x + threadIdx.x;
    if (e < N_EDGE) atomicAdd(&g_hist[tail[e] * 64 + rel[e]], 1);
}

// ---------------------------------------------------------------------------
// Self-loop records + degree from histogram: one warp per node (R1 layout)
__global__ void self_kernel() {
    int lane = threadIdx.x & 31;
    int n = blockIdx.x * (blockDim.x >> 5) + (threadIdx.x >> 5);
    if (n >= N_ENT) return;
    int h0 = g_hist[n * 64 + lane];
    int h1 = g_hist[n * 64 + 32 + lane];
    unsigned tot = __reduce_add_sync(0xffffffffu, (unsigned)(h0 + h1));
    if (lane == 0) g_deg[n] = (int)tot;
    float inv = 1.f / (float)tot;
    float fa0 = 0, fa1 = 0, fm0 = 0, fm1 = 0;
#pragma unroll
    for (int r = 0; r < 64; r++) {
        int hr = (r < 32) ? __shfl_sync(0xffffffffu, h0, r)
                          : __shfl_sync(0xffffffffu, h1, r - 32);
        if (hr) {
            float fh = (float)hr;
            fa0 = fmaf(fh, g_arel[r * 64 + lane],      fa0);
            fa1 = fmaf(fh, g_arel[r * 64 + 32 + lane], fa1);
            fm0 = fmaf(fh, g_mrel[r * 64 + lane],      fm0);
            fm1 = fmaf(fh, g_mrel[r * 64 + 32 + lane], fm1);
        }
    }
    g_self[n * 128 + lane]      = fa0 * inv;
    g_self[n * 128 + 32 + lane] = fa1 * inv;
    g_self[n * 128 + 64 + lane] = fm0 * inv;
    g_self[n * 128 + 96 + lane] = fm1 * inv;
}

// ---------------------------------------------------------------------------
// Exclusive prefix sum over degrees: single block, 1024 threads
__global__ void scan_kernel() {
    __shared__ int s[1024];
    const int T = 1024, C = (N_ENT + T - 1) / T;   // 98 per thread
    int tid = threadIdx.x;
    int base = tid * C;
    int sum = 0;
    for (int i = 0; i < C; i++) {
        int n = base + i;
        if (n < N_ENT) sum += g_deg[n];
    }
    s[tid] = sum;
    __syncthreads();
    for (int d = 1; d < T; d <<= 1) {
        int v = (tid >= d) ? s[tid - d] : 0;
        __syncthreads();
        s[tid] += v;
        __syncthreads();
    }
    int run = tid ? s[tid - 1] : 0;
    for (int i = 0; i < C; i++) {
        int n = base + i;
        if (n < N_ENT) {
            g_off[n] = run;
            g_cursor[n] = run;
            run += g_deg[n];
        }
    }
    if (tid == T - 1) g_off[N_ENT] = run;
}

// ---------------------------------------------------------------------------
// Counting-sort scatter: group (head, rel) by tail
__global__ void scatter_kernel(const int* __restrict__ head,
                               const int* __restrict__ tail,
                               const int* __restrict__ rel) {
    int e = blockIdx.x * blockDim.x + threadIdx.x;
    if (e >= N_EDGE) return;
    int pos = atomicAdd(&g_cursor[tail[e]], 1);
    g_sorted[pos] = make_int2(head[e], rel[e]);
}

// ---------------------------------------------------------------------------
// Segmented softmax-aggregate: one warp per node, 2 edges in flight
// (16 lanes per edge). Accumulates in registers, writes output once.
__global__ void __launch_bounds__(256) aggregate_kernel(
        const float* __restrict__ attn_vec,
        const float* __restrict__ aggr_b,
        float* __restrict__ out) {
    int lane = threadIdx.x & 31;
    int n = blockIdx.x * (blockDim.x >> 5) + (threadIdx.x >> 5);
    if (n >= N_ENT) return;
    int t = lane & 15, sub = lane >> 4;
    unsigned pmask = 3u << (lane & 30);   // the lane pair (t, t^1) within sub

    float4 v  = *(const float4*)(&attn_vec[4 * t]);
    float4 at = *(const float4*)(&g_tailproj[n * 64 + 4 * t]);

    // self-loop edge (counted once: sub 0)
    float4 ah = *(const float4*)(&g_headrec[n * 128 + 4 * t]);
    float4 mh = *(const float4*)(&g_headrec[n * 128 + 64 + 4 * t]);
    float4 ar = *(const float4*)(&g_self[n * 128 + 4 * t]);
    float4 mr = *(const float4*)(&g_self[n * 128 + 64 + 4 * t]);

    float p0 = at.x + ah.x + ar.x; p0 = fmaxf(p0, 0.2f * p0);
    float p1 = at.y + ah.y + ar.y; p1 = fmaxf(p1, 0.2f * p1);
    float p2 = at.z + ah.z + ar.z; p2 = fmaxf(p2, 0.2f * p2);
    float p3 = at.w + ah.w + ar.w; p3 = fmaxf(p3, 0.2f * p3);
    float s = p0 * v.x + p1 * v.y + p2 * v.z + p3 * v.w;
    s += __shfl_xor_sync(0xffffffffu, s, 1);
    float ex = (sub == 0) ? __expf(s) : 0.f;   // logits O(1): max-pass skip safe

    float ax = ex * (mh.x + mr.x);
    float ay = ex * (mh.y + mr.y);
    float az = ex * (mh.z + mr.z);
    float aw = ex * (mh.w + mr.w);
    float den = ex;

    int end = g_off[n + 1];
    for (int i = g_off[n] + sub; i < end; i += 2) {
        int2 e = g_sorted[i];
        ah = *(const float4*)(&g_headrec[e.x * 128 + 4 * t]);
        mh = *(const float4*)(&g_headrec[e.x * 128 + 64 + 4 * t]);
        ar = *(const float4*)(&g_arel[e.y * 64 + 4 * t]);
        mr = *(const float4*)(&g_mrel[e.y * 64 + 4 * t]);

        p0 = at.x + ah.x + ar.x; p0 = fmaxf(p0, 0.2f * p0);
        p1 = at.y + ah.y + ar.y; p1 = fmaxf(p1, 0.2f * p1);
        p2 = at.z + ah.z + ar.z; p2 = fmaxf(p2, 0.2f * p2);
        p3 = at.w + ah.w + ar.w; p3 = fmaxf(p3, 0.2f * p3);
        s = p0 * v.x + p1 * v.y + p2 * v.z + p3 * v.w;
        s += __shfl_xor_sync(pmask, s, 1);     // pair-local: subs may diverge
        ex = __expf(s);

        ax = fmaf(ex, mh.x + mr.x, ax);
        ay = fmaf(ex, mh.y + mr.y, ay);
        az = fmaf(ex, mh.z + mr.z, az);
        aw = fmaf(ex, mh.w + mr.w, aw);
        den += ex;
    }

    // combine the two 16-lane halves (all lanes reconverged here)
    ax  += __shfl_xor_sync(0xffffffffu, ax, 16);
    ay  += __shfl_xor_sync(0xffffffffu, ay, 16);
    az  += __shfl_xor_sync(0xffffffffu, az, 16);
    aw  += __shfl_xor_sync(0xffffffffu, aw, 16);
    den += __shfl_xor_sync(0xffffffffu, den, 16);

    if (sub == 0) {
        float4 b = *(const float4*)(&aggr_b[4 * t]);
        float inv = 1.f / (den + 1e-16f);
        float4 o = make_float4(fmaf(ax, inv, b.x), fmaf(ay, inv, b.y),
                               fmaf(az, inv, b.z), fmaf(aw, inv, b.w));
        *(float4*)(&out[n * 64 + 4 * t]) = o;
    }
}

// ---------------------------------------------------------------------------
extern "C" void kernel_launch(void* const* d_in, const int* in_sizes, int n_in,
                              void* d_out, int out_size) {
    const float* emb_ent  = (const float*)d_in[0];
    const float* emb_rel  = (const float*)d_in[1];
    const float* attn_W   = (const float*)d_in[2];
    const float* attn_b   = (const float*)d_in[3];
    const float* attn_vec = (const float*)d_in[4];
    const float* aggr_W   = (const float*)d_in[5];
    const float* aggr_b   = (const float*)d_in[6];
    const int*   head     = (const int*)d_in[7];
    const int*   tail     = (const int*)d_in[8];
    const int*   rel      = (const int*)d_in[9];
    float*       out      = (float*)d_out;

    void* p_hist;
    cudaGetSymbolAddress(&p_hist, g_hist);
    cudaMemsetAsync(p_hist, 0, sizeof(int) * N_ENT * 64);

    rel_tables_kernel<<<1, 64>>>(emb_rel, attn_W, attn_b, aggr_W);
    node_proj_kernel<<<2048, 256>>>(emb_ent, attn_W, aggr_W);
    hist_kernel<<<(N_EDGE + 255) / 256, 256>>>(tail, rel);
    self_kernel<<<(N_ENT + 7) / 8, 256>>>();
    scan_kernel<<<1, 1024>>>();
    scatter_kernel<<<(N_EDGE + 255) / 256, 256>>>(head, tail, rel);
    aggregate_kernel<<<(N_ENT + 7) / 8, 256>>>(attn_vec, aggr_b, out);
}

// round 4
// speedup vs baseline: 1.2353x; 1.2353x over previous
#include <cuda_runtime.h>

#define N_ENT  100000
#define N_EDGE 1600000
#define N_REL  64
#define N_TOT  (N_EDGE + N_ENT)   // 1,700,000 (even)

// Scratch (allocation-free rule: __device__ globals)
static __device__ float g_tailproj[N_ENT * 64];    // W_t · emb[n]
static __device__ float g_headrec [N_ENT * 128];   // [W_h·emb | M_h·emb]
static __device__ float g_self    [N_ENT * 128];   // [W_r·self_rel + b | M_r·self_rel]
static __device__ float g_selfrel [N_ENT * 32];    // mean incoming rel embedding
static __device__ float g_arel    [N_REL * 64];    // W_r·emb_rel[r] + attn_b
static __device__ float g_mrel    [N_REL * 64];    // M_r·emb_rel[r]
static __device__ int   g_hist    [N_ENT * 64];    // per-node relation histogram
static __device__ float g_sum     [N_ENT * 8];     // softmax denominators
static __device__ float g_acc     [N_ENT * 64];    // unnormalized output accumulator

// ---------------------------------------------------------------------------
// Per-relation tables (for real edges): a_rel[r] = W_r·emb_rel[r] + attn_b
//                                       m_rel[r] = M_r·emb_rel[r]
__global__ void rel_tables_kernel(const float* __restrict__ emb_rel,
                                  const float* __restrict__ attn_W,
                                  const float* __restrict__ attn_b,
                                  const float* __restrict__ aggr_W) {
    int r = threadIdx.x;
    if (r >= N_REL) return;
    float ev[32];
#pragma unroll
    for (int k = 0; k < 32; k++) ev[k] = emb_rel[r * 32 + k];
    for (int o = 0; o < 64; o++) {
        float a = attn_b[o], m = 0.f;
#pragma unroll
        for (int k = 0; k < 32; k++) {
            a = fmaf(attn_W[o * 96 + 64 + k], ev[k], a);
            m = fmaf(aggr_W[o * 64 + 32 + k], ev[k], m);
        }
        g_arel[r * 64 + o] = a;
        g_mrel[r * 64 + o] = m;
    }
}

// ---------------------------------------------------------------------------
// Relation histogram per tail node (one int atomic per edge)
__global__ void hist_kernel(const int* __restrict__ tail,
                            const int* __restrict__ rel) {
    int e = blockIdx.x * blockDim.x + threadIdx.x;
    if (e < N_EDGE) atomicAdd(&g_hist[tail[e] * 64 + rel[e]], 1);
}

// ---------------------------------------------------------------------------
// Mean incoming relation embedding per node (32-dim): one warp per node.
// 4x less table traffic than projecting the 64-dim record here.
__global__ void selfrel_kernel(const float* __restrict__ emb_rel) {
    __shared__ float s_rel[N_REL * 32];   // 8KB
    for (int i = threadIdx.x; i < N_REL * 32; i += blockDim.x)
        s_rel[i] = emb_rel[i];
    __syncthreads();
    int lane = threadIdx.x & 31;
    int n = blockIdx.x * (blockDim.x >> 5) + (threadIdx.x >> 5);
    if (n >= N_ENT) return;
    int h0 = g_hist[n * 64 + lane];
    int h1 = g_hist[n * 64 + 32 + lane];
    float inv = 1.f / (float)__reduce_add_sync(0xffffffffu, (unsigned)(h0 + h1));
    float acc = 0.f;
#pragma unroll
    for (int r = 0; r < 64; r++) {
        int hr = (r < 32) ? __shfl_sync(0xffffffffu, h0, r)
                          : __shfl_sync(0xffffffffu, h1, r - 32);
        if (hr) acc = fmaf((float)hr, s_rel[r * 32 + lane], acc);
    }
    g_selfrel[n * 32 + lane] = acc * inv;
}

// ---------------------------------------------------------------------------
// Per-node projections (5 GEMVs fused): one warp per node, lane = out dim
// pair. emb_ent -> W_t, W_h, M_h ; self_rel -> W_r(+b), M_r.
__global__ void node_proj_kernel(const float* __restrict__ emb_ent,
                                 const float* __restrict__ attn_W,
                                 const float* __restrict__ attn_b,
                                 const float* __restrict__ aggr_W) {
    __shared__ float s_t[2048], s_h[2048], s_m[2048], s_wr[2048], s_mr[2048];
    for (int i = threadIdx.x; i < 2048; i += blockDim.x) {
        int k = i >> 6, o = i & 63;
        s_t[i]  = attn_W[o * 96 + k];
        s_h[i]  = attn_W[o * 96 + 32 + k];
        s_wr[i] = attn_W[o * 96 + 64 + k];
        s_m[i]  = aggr_W[o * 64 + k];
        s_mr[i] = aggr_W[o * 64 + 32 + k];
    }
    __syncthreads();
    int lane = threadIdx.x & 31;
    int warp = threadIdx.x >> 5;
    int wpb  = blockDim.x >> 5;
    float bb0 = attn_b[lane], bb1 = attn_b[32 + lane];
    for (int n = blockIdx.x * wpb + warp; n < N_ENT; n += gridDim.x * wpb) {
        float e  = emb_ent[n * 32 + lane];
        float sr = g_selfrel[n * 32 + lane];
        float a0 = 0, a1 = 0, b0 = 0, b1 = 0, m0 = 0, m1 = 0;
        float c0 = bb0, c1 = bb1, d0 = 0, d1 = 0;
#pragma unroll
        for (int k = 0; k < 32; k++) {
            float ek = __shfl_sync(0xffffffffu, e,  k);
            float sk = __shfl_sync(0xffffffffu, sr, k);
            a0 = fmaf(s_t[k * 64 + lane],       ek, a0);
            a1 = fmaf(s_t[k * 64 + 32 + lane],  ek, a1);
            b0 = fmaf(s_h[k * 64 + lane],       ek, b0);
            b1 = fmaf(s_h[k * 64 + 32 + lane],  ek, b1);
            m0 = fmaf(s_m[k * 64 + lane],       ek, m0);
            m1 = fmaf(s_m[k * 64 + 32 + lane],  ek, m1);
            c0 = fmaf(s_wr[k * 64 + lane],      sk, c0);
            c1 = fmaf(s_wr[k * 64 + 32 + lane], sk, c1);
            d0 = fmaf(s_mr[k * 64 + lane],      sk, d0);
            d1 = fmaf(s_mr[k * 64 + 32 + lane], sk, d1);
        }
        g_tailproj[n * 64 + lane]       = a0;
        g_tailproj[n * 64 + 32 + lane]  = a1;
        g_headrec[n * 128 + lane]       = b0;
        g_headrec[n * 128 + 32 + lane]  = b1;
        g_headrec[n * 128 + 64 + lane]  = m0;
        g_headrec[n * 128 + 96 + lane]  = m1;
        g_self[n * 128 + lane]          = c0;
        g_self[n * 128 + 32 + lane]     = c1;
        g_self[n * 128 + 64 + lane]     = d0;
        g_self[n * 128 + 96 + lane]     = d1;
    }
}

// ---------------------------------------------------------------------------
// Fused edge pass (R1 version): 16 lanes per edge (2 edges/warp). Computes
// exp(logit), atomically accumulates denominator and exp-weighted message.
__global__ void edge_kernel(const int* __restrict__ head,
                            const int* __restrict__ tail,
                            const int* __restrict__ rel,
                            const float* __restrict__ attn_vec) {
    int gw   = (blockIdx.x * blockDim.x + threadIdx.x) >> 5;
    int lane = threadIdx.x & 31;
    int t    = lane & 15;
    int e    = gw * 2 + (lane >> 4);
    if (e >= N_TOT) return;   // never taken (exact grid); keeps shfl mask valid

    int hn, tn;
    const float *ar, *mr;
    if (e < N_EDGE) {
        hn = head[e]; tn = tail[e];
        int r = rel[e];
        ar = &g_arel[r * 64];
        mr = &g_mrel[r * 64];
    } else {
        int n = e - N_EDGE;
        hn = n; tn = n;
        ar = &g_self[n * 128];
        mr = &g_self[n * 128 + 64];
    }

    float4 at  = *(const float4*)(&g_tailproj[tn * 64 + 4 * t]);
    float4 ah  = *(const float4*)(&g_headrec[hn * 128 + 4 * t]);
    float4 mh  = *(const float4*)(&g_headrec[hn * 128 + 64 + 4 * t]);
    float4 arv = *(const float4*)(ar + 4 * t);
    float4 mrv = *(const float4*)(mr + 4 * t);
    float4 v   = *(const float4*)(&attn_vec[4 * t]);

    float p0 = at.x + ah.x + arv.x; p0 = fmaxf(p0, 0.2f * p0);  // leaky_relu
    float p1 = at.y + ah.y + arv.y; p1 = fmaxf(p1, 0.2f * p1);
    float p2 = at.z + ah.z + arv.z; p2 = fmaxf(p2, 0.2f * p2);
    float p3 = at.w + ah.w + arv.w; p3 = fmaxf(p3, 0.2f * p3);

    float s = p0 * v.x + p1 * v.y + p2 * v.z + p3 * v.w;
    s += __shfl_xor_sync(0xffffffffu, s, 1);      // head = t>>1 spans lane pairs
    float ex = __expf(s);                          // logits ~O(1): max-pass safe to skip

    if (!(t & 1)) atomicAdd(&g_sum[tn * 8 + (t >> 1)], ex);

    float mx = ex * (mh.x + mrv.x);
    float my = ex * (mh.y + mrv.y);
    float mz = ex * (mh.z + mrv.z);
    float mw = ex * (mh.w + mrv.w);
    float* dst = &g_acc[tn * 64 + 4 * t];
    asm volatile("red.global.add.v4.f32 [%0], {%1,%2,%3,%4};"
                 :: "l"(dst), "f"(mx), "f"(my), "f"(mz), "f"(mw) : "memory");
}

// ---------------------------------------------------------------------------
// out = acc / (sum + 1e-16) + aggr_b (bias commutes through softmax weights)
__global__ void final_kernel(float* __restrict__ out,
                             const float* __restrict__ aggr_b) {
    int i = blockIdx.x * blockDim.x + threadIdx.x;
    if (i >= N_ENT * 64) return;
    int n = i >> 6, j = i & 63;
    out[i] = g_acc[i] / (g_sum[n * 8 + (j >> 3)] + 1e-16f) + aggr_b[j];
}

// ---------------------------------------------------------------------------
extern "C" void kernel_launch(void* const* d_in, const int* in_sizes, int n_in,
                              void* d_out, int out_size) {
    const float* emb_ent  = (const float*)d_in[0];
    const float* emb_rel  = (const float*)d_in[1];
    const float* attn_W   = (const float*)d_in[2];
    const float* attn_b   = (const float*)d_in[3];
    const float* attn_vec = (const float*)d_in[4];
    const float* aggr_W   = (const float*)d_in[5];
    const float* aggr_b   = (const float*)d_in[6];
    const int*   head     = (const int*)d_in[7];
    const int*   tail     = (const int*)d_in[8];
    const int*   rel      = (const int*)d_in[9];
    float*       out      = (float*)d_out;

    void *p_hist, *p_sum, *p_acc;
    cudaGetSymbolAddress(&p_hist, g_hist);
    cudaGetSymbolAddress(&p_sum,  g_sum);
    cudaGetSymbolAddress(&p_acc,  g_acc);
    cudaMemsetAsync(p_hist, 0, sizeof(int)   * N_ENT * 64);
    cudaMemsetAsync(p_sum,  0, sizeof(float) * N_ENT * 8);
    cudaMemsetAsync(p_acc,  0, sizeof(float) * N_ENT * 64);

    rel_tables_kernel<<<1, 64>>>(emb_rel, attn_W, attn_b, aggr_W);
    hist_kernel<<<(N_EDGE + 255) / 256, 256>>>(tail, rel);
    selfrel_kernel<<<(N_ENT + 7) / 8, 256>>>(emb_rel);
    node_proj_kernel<<<1184, 256>>>(emb_ent, attn_W, attn_b, aggr_W);
    edge_kernel<<<N_TOT / 16, 256>>>(head, tail, rel, attn_vec);
    final_kernel<<<(N_ENT * 64 + 255) / 256, 256>>>(out, aggr_b);
}

// round 5
// speedup vs baseline: 1.5117x; 1.2238x over previous
#include <cuda_runtime.h>

#define N_ENT  100000
#define N_EDGE 1600000
#define N_REL  64
#define N_TOT  (N_EDGE + N_ENT)   // 1,700,000 (even)

// Scratch (allocation-free rule: __device__ globals)
static __device__ float g_tailproj[N_ENT * 64];    // W_t · emb[n]
static __device__ float g_headrec [N_ENT * 128];   // [W_h·emb | M_h·emb]
static __device__ float g_self    [N_ENT * 128];   // [W_r·self_rel + b | M_r·self_rel]
static __device__ float g_selfrel [N_ENT * 32];    // mean incoming rel embedding
static __device__ float g_arel    [N_REL * 64];    // W_r·emb_rel[r] + attn_b
static __device__ float g_mrel    [N_REL * 64];    // M_r·emb_rel[r]
static __device__ int   g_hist    [N_ENT * 64];    // per-node relation histogram
static __device__ float g_sum     [N_ENT * 8];     // softmax denominators
static __device__ float g_acc     [N_ENT * 64];    // unnormalized output accumulator

typedef unsigned long long u64;

__device__ __forceinline__ u64 pack2(float lo, float hi) {
    u64 r;
    asm("mov.b64 %0, {%1, %2};" : "=l"(r) : "f"(lo), "f"(hi));
    return r;
}
__device__ __forceinline__ void unpack2(u64 v, float& lo, float& hi) {
    asm("mov.b64 {%0, %1}, %2;" : "=f"(lo), "=f"(hi) : "l"(v));
}
__device__ __forceinline__ u64 fma2(u64 a, u64 b, u64 c) {
    u64 d;
    asm("fma.rn.f32x2 %0, %1, %2, %3;" : "=l"(d) : "l"(a), "l"(b), "l"(c));
    return d;
}

// ---------------------------------------------------------------------------
// Per-relation tables (for real edges): a_rel[r] = W_r·emb_rel[r] + attn_b
//                                       m_rel[r] = M_r·emb_rel[r]
__global__ void rel_tables_kernel(const float* __restrict__ emb_rel,
                                  const float* __restrict__ attn_W,
                                  const float* __restrict__ attn_b,
                                  const float* __restrict__ aggr_W) {
    int r = threadIdx.x;
    if (r >= N_REL) return;
    float ev[32];
#pragma unroll
    for (int k = 0; k < 32; k++) ev[k] = emb_rel[r * 32 + k];
    for (int o = 0; o < 64; o++) {
        float a = attn_b[o], m = 0.f;
#pragma unroll
        for (int k = 0; k < 32; k++) {
            a = fmaf(attn_W[o * 96 + 64 + k], ev[k], a);
            m = fmaf(aggr_W[o * 64 + 32 + k], ev[k], m);
        }
        g_arel[r * 64 + o] = a;
        g_mrel[r * 64 + o] = m;
    }
}

// ---------------------------------------------------------------------------
// Relation histogram per tail node (one int atomic per edge)
__global__ void hist_kernel(const int* __restrict__ tail,
                            const int* __restrict__ rel) {
    int e = blockIdx.x * blockDim.x + threadIdx.x;
    if (e < N_EDGE) atomicAdd(&g_hist[tail[e] * 64 + rel[e]], 1);
}

// ---------------------------------------------------------------------------
// Mean incoming relation embedding per node (32-dim): one warp per node.
__global__ void selfrel_kernel(const float* __restrict__ emb_rel) {
    __shared__ float s_rel[N_REL * 32];   // 8KB
    for (int i = threadIdx.x; i < N_REL * 32; i += blockDim.x)
        s_rel[i] = emb_rel[i];
    __syncthreads();
    int lane = threadIdx.x & 31;
    int n = blockIdx.x * (blockDim.x >> 5) + (threadIdx.x >> 5);
    if (n >= N_ENT) return;
    int h0 = g_hist[n * 64 + lane];
    int h1 = g_hist[n * 64 + 32 + lane];
    float inv = 1.f / (float)__reduce_add_sync(0xffffffffu, (unsigned)(h0 + h1));
    float acc = 0.f;
#pragma unroll
    for (int r = 0; r < 64; r++) {
        int hr = (r < 32) ? __shfl_sync(0xffffffffu, h0, r)
                          : __shfl_sync(0xffffffffu, h1, r - 32);
        if (hr) acc = fmaf((float)hr, s_rel[r * 32 + lane], acc);
    }
    g_selfrel[n * 32 + lane] = acc * inv;
}

// ---------------------------------------------------------------------------
// Per-node projections (5 GEMVs fused): 4 nodes per warp per k-step, weights
// packed as (o=lane, o=lane+32) float2 pairs -> LDS.64 + fma.rn.f32x2.
__global__ void __launch_bounds__(256) node_proj_kernel(
        const float* __restrict__ emb_ent,
        const float* __restrict__ attn_W,
        const float* __restrict__ attn_b,
        const float* __restrict__ aggr_W) {
    // [proj][k*32 + lane] = (w[lane][k], w[lane+32][k]); 5 * 8KB = 40KB
    __shared__ float2 s_w[5][32 * 32];
    for (int i = threadIdx.x; i < 1024; i += blockDim.x) {
        int k = i >> 5, l = i & 31;
        s_w[0][i] = make_float2(attn_W[l * 96 + k],      attn_W[(l + 32) * 96 + k]);
        s_w[1][i] = make_float2(attn_W[l * 96 + 32 + k], attn_W[(l + 32) * 96 + 32 + k]);
        s_w[2][i] = make_float2(attn_W[l * 96 + 64 + k], attn_W[(l + 32) * 96 + 64 + k]);
        s_w[3][i] = make_float2(aggr_W[l * 64 + k],      aggr_W[(l + 32) * 64 + k]);
        s_w[4][i] = make_float2(aggr_W[l * 64 + 32 + k], aggr_W[(l + 32) * 64 + 32 + k]);
    }
    __syncthreads();

    int lane = threadIdx.x & 31;
    int gw   = blockIdx.x * (blockDim.x >> 5) + (threadIdx.x >> 5);
    int GW   = gridDim.x * (blockDim.x >> 5);
    u64 bias = pack2(attn_b[lane], attn_b[32 + lane]);

    for (int base = gw * 4; base < N_ENT; base += GW * 4) {   // N_ENT % 4 == 0
        float e0 = emb_ent[(base + 0) * 32 + lane];
        float e1 = emb_ent[(base + 1) * 32 + lane];
        float e2 = emb_ent[(base + 2) * 32 + lane];
        float e3 = emb_ent[(base + 3) * 32 + lane];
        float r0 = g_selfrel[(base + 0) * 32 + lane];
        float r1 = g_selfrel[(base + 1) * 32 + lane];
        float r2 = g_selfrel[(base + 2) * 32 + lane];
        float r3 = g_selfrel[(base + 3) * 32 + lane];

        u64 A[4], B[4], C[4], M[4], D[4];
#pragma unroll
        for (int i = 0; i < 4; i++) { A[i] = 0; B[i] = 0; C[i] = bias; M[i] = 0; D[i] = 0; }

#pragma unroll
        for (int k = 0; k < 32; k++) {
            u64 w0 = *(const u64*)&s_w[0][k * 32 + lane];
            u64 w1 = *(const u64*)&s_w[1][k * 32 + lane];
            u64 w2 = *(const u64*)&s_w[2][k * 32 + lane];
            u64 w3 = *(const u64*)&s_w[3][k * 32 + lane];
            u64 w4 = *(const u64*)&s_w[4][k * 32 + lane];
            float ek[4], sk[4];
            ek[0] = __shfl_sync(0xffffffffu, e0, k);
            ek[1] = __shfl_sync(0xffffffffu, e1, k);
            ek[2] = __shfl_sync(0xffffffffu, e2, k);
            ek[3] = __shfl_sync(0xffffffffu, e3, k);
            sk[0] = __shfl_sync(0xffffffffu, r0, k);
            sk[1] = __shfl_sync(0xffffffffu, r1, k);
            sk[2] = __shfl_sync(0xffffffffu, r2, k);
            sk[3] = __shfl_sync(0xffffffffu, r3, k);
#pragma unroll
            for (int i = 0; i < 4; i++) {
                u64 ekk = pack2(ek[i], ek[i]);
                u64 skk = pack2(sk[i], sk[i]);
                A[i] = fma2(w0, ekk, A[i]);
                B[i] = fma2(w1, ekk, B[i]);
                C[i] = fma2(w2, skk, C[i]);
                M[i] = fma2(w3, ekk, M[i]);
                D[i] = fma2(w4, skk, D[i]);
            }
        }

#pragma unroll
        for (int i = 0; i < 4; i++) {
            int n = base + i;
            float lo, hi;
            unpack2(A[i], lo, hi);
            g_tailproj[n * 64 + lane]      = lo;
            g_tailproj[n * 64 + 32 + lane] = hi;
            unpack2(B[i], lo, hi);
            g_headrec[n * 128 + lane]      = lo;
            g_headrec[n * 128 + 32 + lane] = hi;
            unpack2(M[i], lo, hi);
            g_headrec[n * 128 + 64 + lane] = lo;
            g_headrec[n * 128 + 96 + lane] = hi;
            unpack2(C[i], lo, hi);
            g_self[n * 128 + lane]         = lo;
            g_self[n * 128 + 32 + lane]    = hi;
            unpack2(D[i], lo, hi);
            g_self[n * 128 + 64 + lane]    = lo;
            g_self[n * 128 + 96 + lane]    = hi;
        }
    }
}

// ---------------------------------------------------------------------------
// Fused edge pass (R1 version): 16 lanes per edge (2 edges/warp). Computes
// exp(logit), atomically accumulates denominator and exp-weighted message.
__global__ void edge_kernel(const int* __restrict__ head,
                            const int* __restrict__ tail,
                            const int* __restrict__ rel,
                            const float* __restrict__ attn_vec) {
    int gw   = (blockIdx.x * blockDim.x + threadIdx.x) >> 5;
    int lane = threadIdx.x & 31;
    int t    = lane & 15;
    int e    = gw * 2 + (lane >> 4);
    if (e >= N_TOT) return;   // never taken (exact grid); keeps shfl mask valid

    int hn, tn;
    const float *ar, *mr;
    if (e < N_EDGE) {
        hn = head[e]; tn = tail[e];
        int r = rel[e];
        ar = &g_arel[r * 64];
        mr = &g_mrel[r * 64];
    } else {
        int n = e - N_EDGE;
        hn = n; tn = n;
        ar = &g_self[n * 128];
        mr = &g_self[n * 128 + 64];
    }

    float4 at  = *(const float4*)(&g_tailproj[tn * 64 + 4 * t]);
    float4 ah  = *(const float4*)(&g_headrec[hn * 128 + 4 * t]);
    float4 mh  = *(const float4*)(&g_headrec[hn * 128 + 64 + 4 * t]);
    float4 arv = *(const float4*)(ar + 4 * t);
    float4 mrv = *(const float4*)(mr + 4 * t);
    float4 v   = *(const float4*)(&attn_vec[4 * t]);

    float p0 = at.x + ah.x + arv.x; p0 = fmaxf(p0, 0.2f * p0);  // leaky_relu
    float p1 = at.y + ah.y + arv.y; p1 = fmaxf(p1, 0.2f * p1);
    float p2 = at.z + ah.z + arv.z; p2 = fmaxf(p2, 0.2f * p2);
    float p3 = at.w + ah.w + arv.w; p3 = fmaxf(p3, 0.2f * p3);

    float s = p0 * v.x + p1 * v.y + p2 * v.z + p3 * v.w;
    s += __shfl_xor_sync(0xffffffffu, s, 1);      // head = t>>1 spans lane pairs
    float ex = __expf(s);                          // logits ~O(1): max-pass safe to skip

    if (!(t & 1)) atomicAdd(&g_sum[tn * 8 + (t >> 1)], ex);

    float mx = ex * (mh.x + mrv.x);
    float my = ex * (mh.y + mrv.y);
    float mz = ex * (mh.z + mrv.z);
    float mw = ex * (mh.w + mrv.w);
    float* dst = &g_acc[tn * 64 + 4 * t];
    asm volatile("red.global.add.v4.f32 [%0], {%1,%2,%3,%4};"
                 :: "l"(dst), "f"(mx), "f"(my), "f"(mz), "f"(mw) : "memory");
}

// ---------------------------------------------------------------------------
// out = acc / (sum + 1e-16) + aggr_b (bias commutes through softmax weights)
__global__ void final_kernel(float* __restrict__ out,
                             const float* __restrict__ aggr_b) {
    int i = blockIdx.x * blockDim.x + threadIdx.x;
    if (i >= N_ENT * 64) return;
    int n = i >> 6, j = i & 63;
    out[i] = g_acc[i] / (g_sum[n * 8 + (j >> 3)] + 1e-16f) + aggr_b[j];
}

// ---------------------------------------------------------------------------
extern "C" void kernel_launch(void* const* d_in, const int* in_sizes, int n_in,
                              void* d_out, int out_size) {
    const float* emb_ent  = (const float*)d_in[0];
    const float* emb_rel  = (const float*)d_in[1];
    const float* attn_W   = (const float*)d_in[2];
    const float* attn_b   = (const float*)d_in[3];
    const float* attn_vec = (const float*)d_in[4];
    const float* aggr_W   = (const float*)d_in[5];
    const float* aggr_b   = (const float*)d_in[6];
    const int*   head     = (const int*)d_in[7];
    const int*   tail     = (const int*)d_in[8];
    const int*   rel      = (const int*)d_in[9];
    float*       out      = (float*)d_out;

    void *p_hist, *p_sum, *p_acc;
    cudaGetSymbolAddress(&p_hist, g_hist);
    cudaGetSymbolAddress(&p_sum,  g_sum);
    cudaGetSymbolAddress(&p_acc,  g_acc);
    cudaMemsetAsync(p_hist, 0, sizeof(int)   * N_ENT * 64);
    cudaMemsetAsync(p_sum,  0, sizeof(float) * N_ENT * 8);
    cudaMemsetAsync(p_acc,  0, sizeof(float) * N_ENT * 64);

    rel_tables_kernel<<<1, 64>>>(emb_rel, attn_W, attn_b, aggr_W);
    hist_kernel<<<(N_EDGE + 255) / 256, 256>>>(tail, rel);
    selfrel_kernel<<<(N_ENT + 7) / 8, 256>>>(emb_rel);
    node_proj_kernel<<<740, 256>>>(emb_ent, attn_W, attn_b, aggr_W);
    edge_kernel<<<N_TOT / 16, 256>>>(head, tail, rel, attn_vec);
    final_kernel<<<(N_ENT * 64 + 255) / 256, 256>>>(out, aggr_b);
}